// round 8
// baseline (speedup 1.0000x reference)
#include <cuda_runtime.h>
#include <cuda_fp16.h>
#include <math.h>
#include <stdint.h>

// Problem constants
constexpr int Bb = 256;    // batch
constexpr int Tt = 512;    // seq len
constexpr int Ii = 256;    // input size
constexpr int Hh = 512;    // hidden size
constexpr int Oo = 256;    // output size
constexpr int G4 = 4 * Hh; // 2048 packed gate width, n = j*4 + g (0=f,1=i,2=c,3=o)

// ---------------------------------------------------------------------------
// Device scratch
// ---------------------------------------------------------------------------
__device__ __half g_gx[(size_t)Tt * Bb * G4];   // 512 MB: input projections fp16, m = t*B+b
__device__ __half g_xh[(size_t)Tt * Bb * Ii];   // 64 MB: x fp16, [m][k]
__device__ __half g_Wxh[(size_t)G4 * Ii];       // W_x packed [n][k] fp16
__device__ __half g_Whh[(size_t)G4 * Hh];       // W_h packed [n][k] fp16
__device__ float  g_biasp[G4];                  // bias packed [n]
__device__ __half g_hh[2][Bb * Hh];             // double-buffered hidden (fp16)
__device__ unsigned g_ctrs[8];                  // per-b-group barrier counters

// ---------------------------------------------------------------------------
// PTX helpers (base PTX only: valid at compute_103 virtual arch)
// ---------------------------------------------------------------------------
__device__ __forceinline__ uint32_t smem_u32(const void* p) {
    uint32_t a;
    asm("{ .reg .u64 t; cvta.to.shared.u64 t, %1; cvt.u32.u64 %0, t; }" : "=r"(a) : "l"(p));
    return a;
}
__device__ __forceinline__ void cp16(uint32_t dst, const void* src) {
    asm volatile("cp.async.cg.shared.global [%0], [%1], 16;" :: "r"(dst), "l"(src));
}
#define CP_COMMIT() asm volatile("cp.async.commit_group;" ::: "memory")
#define CP_WAIT(n)  asm volatile("cp.async.wait_group %0;" :: "n"(n) : "memory")

__device__ __forceinline__ void ldm_x4(uint32_t (&r)[4], uint32_t addr) {
    asm volatile("ldmatrix.sync.aligned.m8n8.x4.shared.b16 {%0,%1,%2,%3}, [%4];"
        : "=r"(r[0]), "=r"(r[1]), "=r"(r[2]), "=r"(r[3]) : "r"(addr));
}
__device__ __forceinline__ void mma16816(float (&c)[4], const uint32_t (&a)[4], const uint32_t* b) {
    asm volatile("mma.sync.aligned.m16n8k16.row.col.f32.f16.f16.f32 "
        "{%0,%1,%2,%3}, {%4,%5,%6,%7}, {%8,%9}, {%0,%1,%2,%3};"
        : "+f"(c[0]), "+f"(c[1]), "+f"(c[2]), "+f"(c[3])
        : "r"(a[0]), "r"(a[1]), "r"(a[2]), "r"(a[3]), "r"(b[0]), "r"(b[1]));
}

// Fast activations (err ~1e-7, below fp16 noise)
__device__ __forceinline__ float ex2f(float x) { float y; asm("ex2.approx.f32 %0, %1;" : "=f"(y) : "f"(x)); return y; }
__device__ __forceinline__ float rcpf(float x) { float y; asm("rcp.approx.f32 %0, %1;" : "=f"(y) : "f"(x)); return y; }
__device__ __forceinline__ float sigf(float x)   { return rcpf(1.0f + ex2f(-1.4426950408889634f * x)); }
__device__ __forceinline__ float tanhf_(float x) { return __fmaf_rn(2.0f, sigf(2.0f * x), -1.0f); }

// SMEM tile geometry: 64 data halves + 8 pad per row -> conflict-free ldmatrix
constexpr int RSTRIDE = 144;   // bytes per smem row

__device__ __forceinline__ uint32_t a_lane_off(int lane) {
    return (uint32_t)(((lane & 7) + ((lane >> 3) & 1) * 8) * RSTRIDE + (lane >> 4) * 16);
}
__device__ __forceinline__ uint32_t b_lane_off(int lane) {
    return (uint32_t)(((lane & 7) + ((lane >> 4) & 1) * 8) * RSTRIDE + ((lane >> 3) & 1) * 16);
}

// ---------------------------------------------------------------------------
// Packing
// ---------------------------------------------------------------------------
__global__ void pack_x(const float* __restrict__ x) {
    size_t e = ((size_t)blockIdx.x * blockDim.x + threadIdx.x) * 4;
    if (e >= (size_t)Tt * Bb * Ii) return;
    int    k  = (int)(e & 255);
    size_t md = e >> 8;
    int    b  = (int)(md & 255);
    int    t  = (int)(md >> 8);
    float4 v = *(const float4*)(x + ((size_t)b * Tt + t) * Ii + k);
    *(__half2*)(g_xh + e)     = __floats2half2_rn(v.x, v.y);
    *(__half2*)(g_xh + e + 2) = __floats2half2_rn(v.z, v.w);
}

__global__ void pack_w(const float* __restrict__ Wf, const float* __restrict__ bf,
                       const float* __restrict__ Wi, const float* __restrict__ bi,
                       const float* __restrict__ Wc, const float* __restrict__ bc,
                       const float* __restrict__ Wo, const float* __restrict__ bo) {
    int k = blockIdx.x;  // 0..767
    for (int n = threadIdx.x; n < G4; n += blockDim.x) {
        int g = n & 3, j = n >> 2;
        const float* W = (g == 0) ? Wf : (g == 1) ? Wi : (g == 2) ? Wc : Wo;
        float v = W[(size_t)k * Hh + j];
        if (k < Ii) g_Wxh[(size_t)n * Ii + k] = __float2half_rn(v);
        else        g_Whh[(size_t)n * Hh + (k - Ii)] = __float2half_rn(v);
        if (k == 0) {
            const float* bp = (g == 0) ? bf : (g == 1) ? bi : (g == 2) ? bc : bo;
            g_biasp[n] = bp[j];
        }
    }
}

__global__ void zero_state() {
    int i = blockIdx.x * blockDim.x + threadIdx.x;
    if (i < 8) g_ctrs[i] = 0;
    if (i < Bb * Hh) g_hh[0][i] = __float2half_rn(0.0f);
}

// ---------------------------------------------------------------------------
// Phase 1: gx[m][n] = fp16( sum_k xh[m][k] * Wxh[n][k] + bias[n] )
//   CTA 128(M) x 128(N), 256 thr (8 warps = 2m x 4n, 64x32 warp tiles),
//   K=256 in 4 cp.async double-buffered stages.
// ---------------------------------------------------------------------------
constexpr uint32_t P1_A0 = 0,      P1_B0 = 18432;
constexpr uint32_t P1_A1 = 36864,  P1_B1 = 55296;
constexpr int P1_SMEM = 73728;

__global__ void __launch_bounds__(256) phase1_mma() {
    extern __shared__ __align__(128) char smem[];
    const uint32_t sb = smem_u32(smem);
    const int tid = threadIdx.x, lane = tid & 31, wid = tid >> 5;
    const int wm = wid >> 2, wn = wid & 3;
    const int n0 = blockIdx.x * 128;
    const int m0 = blockIdx.y * 128;

    const uint32_t aoff = a_lane_off(lane);
    const uint32_t boff = b_lane_off(lane);

    float acc[4][4][4] = {};

    auto load_stage = [&](int s, uint32_t Ab, uint32_t Bx) {
        const int kb0 = s * 64;
#pragma unroll
        for (int q = 0; q < 4; q++) {                       // A: 128 x 64h
            int i = tid + q * 256, r = i >> 3, g = i & 7;
            cp16(sb + Ab + r * RSTRIDE + g * 16, g_xh + (size_t)(m0 + r) * Ii + kb0 + g * 8);
        }
#pragma unroll
        for (int q = 0; q < 4; q++) {                       // B: 128 x 64h
            int i = tid + q * 256, r = i >> 3, g = i & 7;
            cp16(sb + Bx + r * RSTRIDE + g * 16, g_Wxh + (size_t)(n0 + r) * Ii + kb0 + g * 8);
        }
        CP_COMMIT();
    };
    auto compute = [&](uint32_t Ab, uint32_t Bx) {
#pragma unroll
        for (int kb = 0; kb < 64; kb += 16) {
            uint32_t a[4][4], b[2][4];
#pragma unroll
            for (int mi = 0; mi < 4; mi++)
                ldm_x4(a[mi], sb + Ab + (wm * 64 + mi * 16) * RSTRIDE + kb * 2 + aoff);
#pragma unroll
            for (int bi = 0; bi < 2; bi++)
                ldm_x4(b[bi], sb + Bx + (wn * 32 + bi * 16) * RSTRIDE + kb * 2 + boff);
#pragma unroll
            for (int mi = 0; mi < 4; mi++)
#pragma unroll
                for (int ni = 0; ni < 4; ni++)
                    mma16816(acc[mi][ni], a[mi], &b[ni >> 1][(ni & 1) * 2]);
        }
    };

    load_stage(0, P1_A0, P1_B0);
#pragma unroll
    for (int s = 0; s < 4; s++) {
        if (s < 3) { load_stage(s + 1, (s & 1) ? P1_A0 : P1_A1, (s & 1) ? P1_B0 : P1_B1); CP_WAIT(1); }
        else       { CP_WAIT(0); }
        __syncthreads();
        compute((s & 1) ? P1_A1 : P1_A0, (s & 1) ? P1_B1 : P1_B0);
        __syncthreads();
    }

    // Epilogue: fp16 store with bias
    const int r0 = wm * 64 + (lane >> 2);
    const int c0 = wn * 32 + 2 * (lane & 3);
#pragma unroll
    for (int mi = 0; mi < 4; mi++) {
#pragma unroll
        for (int ni = 0; ni < 4; ni++) {
            const int n = n0 + c0 + ni * 8;
            const float2 bv = *(const float2*)&g_biasp[n];
            const int m = m0 + r0 + mi * 16;
            *(__half2*)(g_gx + (size_t)m * G4 + n) =
                __floats2half2_rn(acc[mi][ni][0] + bv.x, acc[mi][ni][1] + bv.y);
            *(__half2*)(g_gx + (size_t)(m + 8) * G4 + n) =
                __floats2half2_rn(acc[mi][ni][2] + bv.x, acc[mi][ni][3] + bv.y);
        }
    }
}

// ---------------------------------------------------------------------------
// Persistent recurrence, interleaved dual b-groups per CTA.
// Grid 16(n-tiles of 128) x 4(pairs) = 64 CTAs, 128 threads (4 warps along n).
// Each CTA serves b-groups `pair` (rows pair*32..) and `pair+4` (rows
// pair*32+128..). While one group's barrier/load latency drains, the other
// group's GEMM executes. W_h tile (144KB) resident; c in registers; gx in
// register prefetch; per-group spin barriers (fan-in 16).
// ---------------------------------------------------------------------------
constexpr int A_CHUNK = 32 * RSTRIDE;                 // 4608 B
constexpr int B_CHUNK = 128 * RSTRIDE;                // 18432 B
constexpr uint32_t PS_B  = 0;                         // W_h resident: 8 x 18432 = 147456
constexpr uint32_t PS_A0 = 8 * B_CHUNK;               // group A h-chunks: 8 x 4608
constexpr uint32_t PS_A1 = PS_A0 + 8 * A_CHUNK;       // group B h-chunks: 8 x 4608
constexpr int PS_SMEM = (int)(PS_A1 + 8 * A_CHUNK);   // 221184 B
constexpr int CS_STRIDE = 132;                        // Cs[32][132] f32 = 16896 B (overlaps A region)

__global__ void __launch_bounds__(128) lstm_persistent() {
    extern __shared__ __align__(128) char smem[];
    const uint32_t sb = smem_u32(smem);
    const int tid = threadIdx.x, lane = tid & 31, wn = tid >> 5;
    const int n0 = blockIdx.x * 128;
    const int pair = blockIdx.y;
    const int b0A = pair * 32;
    const int b0B = pair * 32 + 128;
    unsigned* const ctrA = &g_ctrs[pair];
    unsigned* const ctrB = &g_ctrs[pair + 4];

    const uint32_t aoff = a_lane_off(lane);
    const uint32_t boff = b_lane_off(lane);

    float* CsA = (float*)(smem + PS_A0);   // overlap group A h region (post-compute)
    float* CsB = (float*)(smem + PS_A1);

    // Epilogue mapping: thread -> (batch row in group, 8-j segment)
    const int erow = tid >> 2, ejq = tid & 3;
    const int j0 = n0 >> 2;
    float cvA[8], cvB[8];
#pragma unroll
    for (int j = 0; j < 8; j++) { cvA[j] = 0.0f; cvB[j] = 0.0f; }

    // Resident W_h tile 128(n) x 512(k): one commit group (folds into first wait)
#pragma unroll
    for (int c = 0; c < 8; c++) {
#pragma unroll
        for (int q = 0; q < 8; q++) {
            int i = tid + q * 128, r = i >> 3, g = i & 7;
            cp16(sb + PS_B + c * B_CHUNK + r * RSTRIDE + g * 16,
                 g_Whh + (size_t)(n0 + r) * Hh + c * 64 + g * 8);
        }
    }
    CP_COMMIT();

    auto issue_loads = [&](uint32_t abase, int b0, const __half* hin) {
#pragma unroll
        for (int c = 0; c < 8; c++) {
#pragma unroll
            for (int q = 0; q < 2; q++) {
                int i = tid + q * 128, r = i >> 3, g = i & 7;
                cp16(abase + c * A_CHUNK + r * RSTRIDE + g * 16,
                     hin + (size_t)(b0 + r) * Hh + c * 64 + g * 8);
            }
            if (c == 3) CP_COMMIT();
        }
        CP_COMMIT();
    };
    auto prefetch_gx = [&](int t, int b0, uint4 (&gxp)[4]) {
        const uint4* gsrc = (const uint4*)(g_gx + ((size_t)t * Bb + b0 + erow) * G4 + n0 + ejq * 32);
#pragma unroll
        for (int i = 0; i < 4; i++) gxp[i] = gsrc[i];
    };
    auto compute_chunk = [&](uint32_t abase, int kc, float (&acc)[2][4][4]) {
        const uint32_t Ab = abase + kc * A_CHUNK;
        const uint32_t Bx = sb + PS_B + kc * B_CHUNK + (wn * 32) * RSTRIDE;
#pragma unroll
        for (int kb = 0; kb < 64; kb += 16) {
            uint32_t a[2][4], b[2][4];
#pragma unroll
            for (int mi = 0; mi < 2; mi++)
                ldm_x4(a[mi], Ab + mi * 16 * RSTRIDE + kb * 2 + aoff);
#pragma unroll
            for (int bi = 0; bi < 2; bi++)
                ldm_x4(b[bi], Bx + bi * 16 * RSTRIDE + kb * 2 + boff);
#pragma unroll
            for (int mi = 0; mi < 2; mi++)
#pragma unroll
                for (int ni = 0; ni < 4; ni++)
                    mma16816(acc[mi][ni], a[mi], &b[ni >> 1][(ni & 1) * 2]);
        }
    };
    // Full group step: compute GEMM, exchange, pointwise, store h; ends with
    // fence+sync so the follow-up arrive is safe.
    auto do_group = [&](uint32_t abase, float* Cs, int b0, float (&cv)[8],
                        const uint4 (&gxp)[4], __half* hout) {
        float acc[2][4][4] = {};
        CP_WAIT(1);             // first 4 h-chunks (plus any older groups)
        __syncthreads();
        compute_chunk(abase, 0, acc); compute_chunk(abase, 1, acc);
        compute_chunk(abase, 2, acc); compute_chunk(abase, 3, acc);
        CP_WAIT(0);
        __syncthreads();
        compute_chunk(abase, 4, acc); compute_chunk(abase, 5, acc);
        compute_chunk(abase, 6, acc); compute_chunk(abase, 7, acc);
        __syncthreads();        // all A reads done -> Cs may overwrite A region

        const int r0 = lane >> 2;
        const int c0 = wn * 32 + 2 * (lane & 3);
#pragma unroll
        for (int mi = 0; mi < 2; mi++) {
#pragma unroll
            for (int ni = 0; ni < 4; ni++) {
                const int rr = r0 + mi * 16, cc = c0 + ni * 8;
                Cs[rr * CS_STRIDE + cc]           = acc[mi][ni][0];
                Cs[rr * CS_STRIDE + cc + 1]       = acc[mi][ni][1];
                Cs[(rr + 8) * CS_STRIDE + cc]     = acc[mi][ni][2];
                Cs[(rr + 8) * CS_STRIDE + cc + 1] = acc[mi][ni][3];
            }
        }
        __syncthreads();

        {
            const float* cs = Cs + erow * CS_STRIDE + ejq * 32;
            const uint32_t* gxh2 = (const uint32_t*)gxp;
            __half hb[8];
#pragma unroll
            for (int j = 0; j < 8; j++) {
                float4 pre = *(const float4*)(cs + j * 4);           // W_h·h (f,i,c,o)
                float2 g01 = __half22float2(*(const __half2*)&gxh2[j * 2]);
                float2 g23 = __half22float2(*(const __half2*)&gxh2[j * 2 + 1]);
                float fg = sigf(pre.x + g01.x);
                float ig = sigf(pre.y + g01.y);
                float gg = tanhf_(pre.z + g23.x);
                float og = sigf(pre.w + g23.y);
                float cn = fg * cv[j] + ig * gg;
                cv[j] = cn;
                hb[j] = __float2half_rn(og * tanhf_(cn));
            }
            *(uint4*)(hout + (size_t)(b0 + erow) * Hh + j0 + ejq * 8) = *(uint4*)hb;
        }
        __threadfence();
        __syncthreads();
    };
    auto arrive = [&](unsigned* ctr) {
        if (tid == 0)
            asm volatile("red.release.gpu.global.add.u32 [%0], %1;"
                         :: "l"(ctr), "r"(1u) : "memory");
    };
    auto waitbar = [&](unsigned* ctr, unsigned target) {
        if (tid == 0) {
            unsigned v;
            do {
                asm volatile("ld.acquire.gpu.global.u32 %0, [%1];"
                             : "=r"(v) : "l"(ctr) : "memory");
            } while (v < target);
        }
        __syncthreads();
    };

    // Prologue: group A step-0 loads (h(0) = 0 already initialized)
    uint4 gxA[4], gxB[4];
    issue_loads(sb + PS_A0, b0A, g_hh[0]);
    prefetch_gx(0, b0A, gxA);

    for (int t = 0; t < Tt; t++) {
        const __half* __restrict__ hin = g_hh[t & 1];
        __half* __restrict__ hout      = g_hh[(t + 1) & 1];

        // --- group A: loads already in flight ---
        do_group(sb + PS_A0, CsA, b0A, cvA, gxA, hout);
        arrive(ctrA);

        // --- group B: wait (hidden by A's compute just done), load, compute ---
        waitbar(ctrB, (unsigned)t * 16u);
        issue_loads(sb + PS_A1, b0B, hin);
        prefetch_gx(t, b0B, gxB);
        do_group(sb + PS_A1, CsB, b0B, cvB, gxB, hout);
        arrive(ctrB);

        // --- next A: wait (hidden by B's compute), issue loads ---
        if (t + 1 < Tt) {
            waitbar(ctrA, (unsigned)(t + 1) * 16u);
            issue_loads(sb + PS_A0, b0A, hout);
            prefetch_gx(t + 1, b0A, gxA);
        }
    }
}

// ---------------------------------------------------------------------------
// Output head: logits = h_last @ Wout + bout; log_softmax per row.
// ---------------------------------------------------------------------------
__global__ __launch_bounds__(256) void final_head(
    const float* __restrict__ Wout, const float* __restrict__ bout,
    float* __restrict__ out)
{
    __shared__ float hs[Hh];
    __shared__ float red[256];

    const int b = blockIdx.x;
    const int o = threadIdx.x;
    const __half* hrow = g_hh[0] + (size_t)b * Hh;   // t=511 wrote buffer 0

    for (int k = o; k < Hh; k += 256) hs[k] = __half2float(hrow[k]);
    __syncthreads();

    float acc = bout[o];
#pragma unroll 4
    for (int k = 0; k < Hh; k++)
        acc += hs[k] * Wout[(size_t)k * Oo + o];

    red[o] = acc;
    __syncthreads();
    for (int s = 128; s > 0; s >>= 1) {
        if (o < s) red[o] = fmaxf(red[o], red[o + s]);
        __syncthreads();
    }
    const float mx = red[0];
    __syncthreads();

    red[o] = expf(acc - mx);
    __syncthreads();
    for (int s = 128; s > 0; s >>= 1) {
        if (o < s) red[o] += red[o + s];
        __syncthreads();
    }
    const float lse = logf(red[0]) + mx;
    out[(size_t)b * Oo + o] = acc - lse;
}

// ---------------------------------------------------------------------------
// kernel_launch
// ---------------------------------------------------------------------------
extern "C" void kernel_launch(void* const* d_in, const int* in_sizes, int n_in,
                              void* d_out, int out_size)
{
    const float* inputs = (const float*)d_in[0];
    const float* Wf = (const float*)d_in[1];
    const float* bf = (const float*)d_in[2];
    const float* Wi = (const float*)d_in[3];
    const float* bi = (const float*)d_in[4];
    const float* Wc = (const float*)d_in[5];
    const float* bc = (const float*)d_in[6];
    const float* Wo = (const float*)d_in[7];
    const float* bo = (const float*)d_in[8];
    const float* Wout = (const float*)d_in[9];
    const float* bout = (const float*)d_in[10];
    float* out = (float*)d_out;

    static bool attr_done = false;
    if (!attr_done) {
        cudaFuncSetAttribute(phase1_mma, cudaFuncAttributeMaxDynamicSharedMemorySize, P1_SMEM);
        cudaFuncSetAttribute(lstm_persistent, cudaFuncAttributeMaxDynamicSharedMemorySize, PS_SMEM);
        attr_done = true;
    }

    pack_x<<<(unsigned)((size_t)Tt * Bb * Ii / 4 / 256), 256>>>(inputs);
    pack_w<<<Ii + Hh, 256>>>(Wf, bf, Wi, bi, Wc, bc, Wo, bo);
    zero_state<<<(Bb * Hh + 255) / 256, 256>>>();

    // Phase 1: M = 131072, N = 2048, K = 256, 128x128 tiles
    phase1_mma<<<dim3(G4 / 128, (Tt * Bb) / 128), 256, P1_SMEM>>>();

    // Persistent recurrence: 16 n-tiles x 4 pairs = 64 CTAs, dual-group interleave
    lstm_persistent<<<dim3(G4 / 128, Bb / 64), 128, PS_SMEM>>>();

    final_head<<<Bb, 256>>>(Wout, bout, out);
}

// round 9
// speedup vs baseline: 1.6098x; 1.6098x over previous
#include <cuda_runtime.h>
#include <cuda_fp16.h>
#include <math.h>
#include <stdint.h>

// Problem constants
constexpr int Bb = 256;    // batch
constexpr int Tt = 512;    // seq len
constexpr int Ii = 256;    // input size
constexpr int Hh = 512;    // hidden size
constexpr int Oo = 256;    // output size
constexpr int G4 = 4 * Hh; // 2048 packed gate width, n = j*4 + g (0=f,1=i,2=c,3=o)

// ---------------------------------------------------------------------------
// Device scratch
// ---------------------------------------------------------------------------
__device__ __half g_gx[(size_t)Tt * Bb * G4];   // 512 MB: input projections fp16, m = t*B+b
__device__ __half g_xh[(size_t)Tt * Bb * Ii];   // 64 MB: x fp16, [m][k]
__device__ __half g_Wxh[(size_t)G4 * Ii];       // W_x packed [n][k] fp16
__device__ __half g_Whh[(size_t)G4 * Hh];       // W_h packed [n][k] fp16
__device__ float  g_biasp[G4];                  // bias packed [n]
__device__ __half g_hh[2][Bb * Hh];             // double-buffered hidden (fp16)
__device__ unsigned g_ctrs[8];                  // per-b-group barrier counters

// ---------------------------------------------------------------------------
// PTX helpers (base PTX only: valid at compute_103 virtual arch)
// ---------------------------------------------------------------------------
__device__ __forceinline__ uint32_t smem_u32(const void* p) {
    uint32_t a;
    asm("{ .reg .u64 t; cvta.to.shared.u64 t, %1; cvt.u32.u64 %0, t; }" : "=r"(a) : "l"(p));
    return a;
}
__device__ __forceinline__ void cp16(uint32_t dst, const void* src) {
    asm volatile("cp.async.cg.shared.global [%0], [%1], 16;" :: "r"(dst), "l"(src));
}
#define CP_COMMIT() asm volatile("cp.async.commit_group;" ::: "memory")
#define CP_WAIT(n)  asm volatile("cp.async.wait_group %0;" :: "n"(n) : "memory")

__device__ __forceinline__ void ldm_x4(uint32_t (&r)[4], uint32_t addr) {
    asm volatile("ldmatrix.sync.aligned.m8n8.x4.shared.b16 {%0,%1,%2,%3}, [%4];"
        : "=r"(r[0]), "=r"(r[1]), "=r"(r[2]), "=r"(r[3]) : "r"(addr));
}
__device__ __forceinline__ void mma16816(float (&c)[4], const uint32_t (&a)[4], const uint32_t* b) {
    asm volatile("mma.sync.aligned.m16n8k16.row.col.f32.f16.f16.f32 "
        "{%0,%1,%2,%3}, {%4,%5,%6,%7}, {%8,%9}, {%0,%1,%2,%3};"
        : "+f"(c[0]), "+f"(c[1]), "+f"(c[2]), "+f"(c[3])
        : "r"(a[0]), "r"(a[1]), "r"(a[2]), "r"(a[3]), "r"(b[0]), "r"(b[1]));
}

// Fast activations (err ~1e-7, below fp16 noise)
__device__ __forceinline__ float ex2f(float x) { float y; asm("ex2.approx.f32 %0, %1;" : "=f"(y) : "f"(x)); return y; }
__device__ __forceinline__ float rcpf(float x) { float y; asm("rcp.approx.f32 %0, %1;" : "=f"(y) : "f"(x)); return y; }
__device__ __forceinline__ float sigf(float x)   { return rcpf(1.0f + ex2f(-1.4426950408889634f * x)); }
__device__ __forceinline__ float tanhf_(float x) { return __fmaf_rn(2.0f, sigf(2.0f * x), -1.0f); }

// SMEM tile geometry: 64 data halves + 8 pad per row -> conflict-free ldmatrix
constexpr int RSTRIDE = 144;   // bytes per smem row

__device__ __forceinline__ uint32_t a_lane_off(int lane) {
    return (uint32_t)(((lane & 7) + ((lane >> 3) & 1) * 8) * RSTRIDE + (lane >> 4) * 16);
}
__device__ __forceinline__ uint32_t b_lane_off(int lane) {
    return (uint32_t)(((lane & 7) + ((lane >> 4) & 1) * 8) * RSTRIDE + ((lane >> 3) & 1) * 16);
}

// ---------------------------------------------------------------------------
// Packing
// ---------------------------------------------------------------------------
__global__ void pack_x(const float* __restrict__ x) {
    size_t e = ((size_t)blockIdx.x * blockDim.x + threadIdx.x) * 4;
    if (e >= (size_t)Tt * Bb * Ii) return;
    int    k  = (int)(e & 255);
    size_t md = e >> 8;
    int    b  = (int)(md & 255);
    int    t  = (int)(md >> 8);
    float4 v = *(const float4*)(x + ((size_t)b * Tt + t) * Ii + k);
    *(__half2*)(g_xh + e)     = __floats2half2_rn(v.x, v.y);
    *(__half2*)(g_xh + e + 2) = __floats2half2_rn(v.z, v.w);
}

__global__ void pack_w(const float* __restrict__ Wf, const float* __restrict__ bf,
                       const float* __restrict__ Wi, const float* __restrict__ bi,
                       const float* __restrict__ Wc, const float* __restrict__ bc,
                       const float* __restrict__ Wo, const float* __restrict__ bo) {
    int k = blockIdx.x;  // 0..767
    for (int n = threadIdx.x; n < G4; n += blockDim.x) {
        int g = n & 3, j = n >> 2;
        const float* W = (g == 0) ? Wf : (g == 1) ? Wi : (g == 2) ? Wc : Wo;
        float v = W[(size_t)k * Hh + j];
        if (k < Ii) g_Wxh[(size_t)n * Ii + k] = __float2half_rn(v);
        else        g_Whh[(size_t)n * Hh + (k - Ii)] = __float2half_rn(v);
        if (k == 0) {
            const float* bp = (g == 0) ? bf : (g == 1) ? bi : (g == 2) ? bc : bo;
            g_biasp[n] = bp[j];
        }
    }
}

__global__ void zero_state() {
    int i = blockIdx.x * blockDim.x + threadIdx.x;
    if (i < 8) g_ctrs[i] = 0;
    if (i < Bb * Hh) g_hh[0][i] = __float2half_rn(0.0f);
}

// ---------------------------------------------------------------------------
// Phase 1: gx[m][n] = fp16( sum_k xh[m][k] * Wxh[n][k] + bias[n] )
//   CTA 128(M) x 128(N), 256 thr (8 warps = 2m x 4n, 64x32 warp tiles),
//   K=256 in 4 cp.async double-buffered stages.
// ---------------------------------------------------------------------------
constexpr uint32_t P1_A0 = 0,      P1_B0 = 18432;
constexpr uint32_t P1_A1 = 36864,  P1_B1 = 55296;
constexpr int P1_SMEM = 73728;

__global__ void __launch_bounds__(256) phase1_mma() {
    extern __shared__ __align__(128) char smem[];
    const uint32_t sb = smem_u32(smem);
    const int tid = threadIdx.x, lane = tid & 31, wid = tid >> 5;
    const int wm = wid >> 2, wn = wid & 3;
    const int n0 = blockIdx.x * 128;
    const int m0 = blockIdx.y * 128;

    const uint32_t aoff = a_lane_off(lane);
    const uint32_t boff = b_lane_off(lane);

    float acc[4][4][4] = {};

    auto load_stage = [&](int s, uint32_t Ab, uint32_t Bx) {
        const int kb0 = s * 64;
#pragma unroll
        for (int q = 0; q < 4; q++) {                       // A: 128 x 64h
            int i = tid + q * 256, r = i >> 3, g = i & 7;
            cp16(sb + Ab + r * RSTRIDE + g * 16, g_xh + (size_t)(m0 + r) * Ii + kb0 + g * 8);
        }
#pragma unroll
        for (int q = 0; q < 4; q++) {                       // B: 128 x 64h
            int i = tid + q * 256, r = i >> 3, g = i & 7;
            cp16(sb + Bx + r * RSTRIDE + g * 16, g_Wxh + (size_t)(n0 + r) * Ii + kb0 + g * 8);
        }
        CP_COMMIT();
    };
    auto compute = [&](uint32_t Ab, uint32_t Bx) {
#pragma unroll
        for (int kb = 0; kb < 64; kb += 16) {
            uint32_t a[4][4], b[2][4];
#pragma unroll
            for (int mi = 0; mi < 4; mi++)
                ldm_x4(a[mi], sb + Ab + (wm * 64 + mi * 16) * RSTRIDE + kb * 2 + aoff);
#pragma unroll
            for (int bi = 0; bi < 2; bi++)
                ldm_x4(b[bi], sb + Bx + (wn * 32 + bi * 16) * RSTRIDE + kb * 2 + boff);
#pragma unroll
            for (int mi = 0; mi < 4; mi++)
#pragma unroll
                for (int ni = 0; ni < 4; ni++)
                    mma16816(acc[mi][ni], a[mi], &b[ni >> 1][(ni & 1) * 2]);
        }
    };

    load_stage(0, P1_A0, P1_B0);
#pragma unroll
    for (int s = 0; s < 4; s++) {
        if (s < 3) { load_stage(s + 1, (s & 1) ? P1_A0 : P1_A1, (s & 1) ? P1_B0 : P1_B1); CP_WAIT(1); }
        else       { CP_WAIT(0); }
        __syncthreads();
        compute((s & 1) ? P1_A1 : P1_A0, (s & 1) ? P1_B1 : P1_B0);
        __syncthreads();
    }

    // Epilogue: fp16 store with bias
    const int r0 = wm * 64 + (lane >> 2);
    const int c0 = wn * 32 + 2 * (lane & 3);
#pragma unroll
    for (int mi = 0; mi < 4; mi++) {
#pragma unroll
        for (int ni = 0; ni < 4; ni++) {
            const int n = n0 + c0 + ni * 8;
            const float2 bv = *(const float2*)&g_biasp[n];
            const int m = m0 + r0 + mi * 16;
            *(__half2*)(g_gx + (size_t)m * G4 + n) =
                __floats2half2_rn(acc[mi][ni][0] + bv.x, acc[mi][ni][1] + bv.y);
            *(__half2*)(g_gx + (size_t)(m + 8) * G4 + n) =
                __floats2half2_rn(acc[mi][ni][2] + bv.x, acc[mi][ni][3] + bv.y);
        }
    }
}

// ---------------------------------------------------------------------------
// Persistent recurrence: 128 CTAs = 16 n-tiles(128) x 8 b-groups(32), all 512
// steps. 128 threads (4 warps = 1m x 4n, 32x32 warp tiles). W_h tile (144KB)
// resident in smem; c in registers; gx prefetched into registers from global;
// per-b-group spin barrier (fan-in 16). Fragment double-buffering overlaps
// ldmatrix latency with HMMA issue inside each K-half.
// ---------------------------------------------------------------------------
constexpr int A_CHUNK = 32 * RSTRIDE;                 // 4608 B  (32 rows x 64 halves)
constexpr int B_CHUNK = 128 * RSTRIDE;                // 18432 B (128 rows x 64 halves)
constexpr uint32_t PS_A  = 0;                         // A (h) chunks: 8 x 4608 = 36864
constexpr uint32_t PS_B  = 8 * A_CHUNK;               // B (Wh) resident: 8 x 18432 = 147456
constexpr uint32_t PS_CS = PS_B + 8 * B_CHUNK;        // Cs exchange: 32 x 132 f32
constexpr int CS_STRIDE = 132;
constexpr int PS_SMEM = PS_CS + 32 * CS_STRIDE * 4;   // 201216 B

__global__ void __launch_bounds__(128) lstm_persistent() {
    extern __shared__ __align__(128) char smem[];
    const uint32_t sb = smem_u32(smem);
    float* Cs = (float*)(smem + PS_CS);
    const int tid = threadIdx.x, lane = tid & 31, wn = tid >> 5;  // 4 warps along n
    const int n0 = blockIdx.x * 128;
    const int b0 = blockIdx.y * 32;
    unsigned* const ctr = &g_ctrs[blockIdx.y];        // per-b-group barrier, fan-in 16

    const uint32_t aoff = a_lane_off(lane);
    const uint32_t boff = b_lane_off(lane);

    // Resident B: W_h tile 128(n) x 512(k), 8 chunks, loaded once.
#pragma unroll
    for (int c = 0; c < 8; c++) {
#pragma unroll
        for (int q = 0; q < 8; q++) {
            int i = tid + q * 128, r = i >> 3, g = i & 7;
            cp16(sb + PS_B + c * B_CHUNK + r * RSTRIDE + g * 16,
                 g_Whh + (size_t)(n0 + r) * Hh + c * 64 + g * 8);
        }
    }
    CP_COMMIT();

    // Epilogue mapping: thread -> (batch row, 8-j segment); c in regs.
    const int erow = tid >> 2, ejq = tid & 3;         // 32 rows x 4 segs
    const int eb = b0 + erow;
    const int j0 = n0 >> 2;
    float cv[8];
#pragma unroll
    for (int j = 0; j < 8; j++) cv[j] = 0.0f;

    CP_WAIT(0);
    __syncthreads();

    // Fragment load for k-iteration idx (idx = chunk*4 + kb/16)
    auto frag_load = [&](int idx, uint32_t (&a)[2][4], uint32_t (&b)[2][4]) {
        const int kc = idx >> 2, kb2 = (idx & 3) * 32;   // kb*2 bytes
        const uint32_t Ab = sb + PS_A + kc * A_CHUNK + kb2 + aoff;
        const uint32_t Bx = sb + PS_B + kc * B_CHUNK + (wn * 32) * RSTRIDE + kb2 + boff;
        ldm_x4(a[0], Ab);
        ldm_x4(a[1], Ab + 16 * RSTRIDE);
        ldm_x4(b[0], Bx);
        ldm_x4(b[1], Bx + 16 * RSTRIDE);
    };
    auto mma_iter = [&](const uint32_t (&a)[2][4], const uint32_t (&b)[2][4],
                        float (&acc)[2][4][4]) {
#pragma unroll
        for (int mi = 0; mi < 2; mi++)
#pragma unroll
            for (int ni = 0; ni < 4; ni++)
                mma16816(acc[mi][ni], a[mi], &b[ni >> 1][(ni & 1) * 2]);
    };
    // One K-half (4 chunks = 16 k-iterations), fragments double-buffered.
    auto compute_half = [&](int base, float (&acc)[2][4][4]) {
        uint32_t af[2][2][4], bf[2][2][4];
        frag_load(base, af[0], bf[0]);
#pragma unroll
        for (int i = 0; i < 16; i++) {
            if (i < 15) frag_load(base + i + 1, af[(i + 1) & 1], bf[(i + 1) & 1]);
            mma_iter(af[i & 1], bf[i & 1], acc);
        }
    };
    auto load_hchunk = [&](const __half* hin, int c) {
#pragma unroll
        for (int q = 0; q < 2; q++) {
            int i = tid + q * 128, r = i >> 3, g = i & 7;
            cp16(sb + PS_A + c * A_CHUNK + r * RSTRIDE + g * 16,
                 hin + (size_t)(b0 + r) * Hh + c * 64 + g * 8);
        }
    };

    for (int t = 0; t < Tt; t++) {
        const __half* __restrict__ hin  = g_hh[t & 1];
        __half* __restrict__ hout       = g_hh[(t + 1) & 1];

        // gx(t) prefetch into registers (no barrier dependency; consumed ~2us later)
        uint4 gxp[4];
        {
            const uint4* gsrc = (const uint4*)(g_gx + ((size_t)t * Bb + eb) * G4 + n0 + ejq * 32);
#pragma unroll
            for (int i = 0; i < 4; i++) gxp[i] = gsrc[i];
        }

        // h loads: 2 commit groups of 4 chunks
        load_hchunk(hin, 0); load_hchunk(hin, 1);
        load_hchunk(hin, 2); load_hchunk(hin, 3); CP_COMMIT();
        load_hchunk(hin, 4); load_hchunk(hin, 5);
        load_hchunk(hin, 6); load_hchunk(hin, 7); CP_COMMIT();

        float acc[2][4][4] = {};
        CP_WAIT(1);
        __syncthreads();
        compute_half(0, acc);
        CP_WAIT(0);
        __syncthreads();
        compute_half(16, acc);

        // Exchange accumulators through smem (Cs[32][132])
        const int r0 = lane >> 2;
        const int c0 = wn * 32 + 2 * (lane & 3);
#pragma unroll
        for (int mi = 0; mi < 2; mi++) {
#pragma unroll
            for (int ni = 0; ni < 4; ni++) {
                const int rr = r0 + mi * 16, cc = c0 + ni * 8;
                Cs[rr * CS_STRIDE + cc]           = acc[mi][ni][0];
                Cs[rr * CS_STRIDE + cc + 1]       = acc[mi][ni][1];
                Cs[(rr + 8) * CS_STRIDE + cc]     = acc[mi][ni][2];
                Cs[(rr + 8) * CS_STRIDE + cc + 1] = acc[mi][ni][3];
            }
        }
        __syncthreads();

        // Pointwise LSTM update: 8 j's per thread; gx from registers
        {
            const float* cs = Cs + erow * CS_STRIDE + ejq * 32;
            const uint32_t* gxh2 = (const uint32_t*)gxp;   // 8 x (2 halves) pairs
            __half hb[8];
#pragma unroll
            for (int j = 0; j < 8; j++) {
                float4 pre = *(const float4*)(cs + j * 4);           // W_h·h (f,i,c,o)
                float2 g01 = __half22float2(*(const __half2*)&gxh2[j * 2]);
                float2 g23 = __half22float2(*(const __half2*)&gxh2[j * 2 + 1]);
                float fg = sigf(pre.x + g01.x);
                float ig = sigf(pre.y + g01.y);
                float gg = tanhf_(pre.z + g23.x);
                float og = sigf(pre.w + g23.y);
                float cn = fg * cv[j] + ig * gg;
                cv[j] = cn;
                hb[j] = __float2half_rn(og * tanhf_(cn));
            }
            *(uint4*)(hout + (size_t)eb * Hh + j0 + ejq * 8) = *(uint4*)hb;
        }

        // Per-b-group barrier: release h(t+1), tight acquire spin
        asm volatile("fence.acq_rel.gpu;" ::: "memory");
        __syncthreads();
        if (tid == 0) {
            asm volatile("red.release.gpu.global.add.u32 [%0], %1;"
                         :: "l"(ctr), "r"(1u) : "memory");
            const unsigned target = (unsigned)(t + 1) * 16u;
            unsigned v;
            do {
                asm volatile("ld.acquire.gpu.global.u32 %0, [%1];"
                             : "=r"(v) : "l"(ctr) : "memory");
            } while (v < target);
        }
        __syncthreads();
    }
}

// ---------------------------------------------------------------------------
// Output head: logits = h_last @ Wout + bout; log_softmax per row.
// ---------------------------------------------------------------------------
__global__ __launch_bounds__(256) void final_head(
    const float* __restrict__ Wout, const float* __restrict__ bout,
    float* __restrict__ out)
{
    __shared__ float hs[Hh];
    __shared__ float red[256];

    const int b = blockIdx.x;
    const int o = threadIdx.x;
    const __half* hrow = g_hh[0] + (size_t)b * Hh;   // t=511 wrote buffer 0

    for (int k = o; k < Hh; k += 256) hs[k] = __half2float(hrow[k]);
    __syncthreads();

    float acc = bout[o];
#pragma unroll 4
    for (int k = 0; k < Hh; k++)
        acc += hs[k] * Wout[(size_t)k * Oo + o];

    red[o] = acc;
    __syncthreads();
    for (int s = 128; s > 0; s >>= 1) {
        if (o < s) red[o] = fmaxf(red[o], red[o + s]);
        __syncthreads();
    }
    const float mx = red[0];
    __syncthreads();

    red[o] = expf(acc - mx);
    __syncthreads();
    for (int s = 128; s > 0; s >>= 1) {
        if (o < s) red[o] += red[o + s];
        __syncthreads();
    }
    const float lse = logf(red[0]) + mx;
    out[(size_t)b * Oo + o] = acc - lse;
}

// ---------------------------------------------------------------------------
// kernel_launch
// ---------------------------------------------------------------------------
extern "C" void kernel_launch(void* const* d_in, const int* in_sizes, int n_in,
                              void* d_out, int out_size)
{
    const float* inputs = (const float*)d_in[0];
    const float* Wf = (const float*)d_in[1];
    const float* bf = (const float*)d_in[2];
    const float* Wi = (const float*)d_in[3];
    const float* bi = (const float*)d_in[4];
    const float* Wc = (const float*)d_in[5];
    const float* bc = (const float*)d_in[6];
    const float* Wo = (const float*)d_in[7];
    const float* bo = (const float*)d_in[8];
    const float* Wout = (const float*)d_in[9];
    const float* bout = (const float*)d_in[10];
    float* out = (float*)d_out;

    static bool attr_done = false;
    if (!attr_done) {
        cudaFuncSetAttribute(phase1_mma, cudaFuncAttributeMaxDynamicSharedMemorySize, P1_SMEM);
        cudaFuncSetAttribute(lstm_persistent, cudaFuncAttributeMaxDynamicSharedMemorySize, PS_SMEM);
        attr_done = true;
    }

    pack_x<<<(unsigned)((size_t)Tt * Bb * Ii / 4 / 256), 256>>>(inputs);
    pack_w<<<Ii + Hh, 256>>>(Wf, bf, Wi, bi, Wc, bc, Wo, bo);
    zero_state<<<(Bb * Hh + 255) / 256, 256>>>();

    // Phase 1: M = 131072, N = 2048, K = 256, 128x128 tiles
    phase1_mma<<<dim3(G4 / 128, (Tt * Bb) / 128), 256, P1_SMEM>>>();

    // Persistent recurrence: 16 n-tiles x 8 b-groups = 128 CTAs, single wave
    lstm_persistent<<<dim3(G4 / 128, Bb / 32), 128, PS_SMEM>>>();

    final_head<<<Bb, 256>>>(Wout, bout, out);
}